// round 6
// baseline (speedup 1.0000x reference)
#include <cuda_runtime.h>
#include <cstdint>

// ----------------------------------------------------------------------------
// DCRNN decoder cell (2 layers), N=2048, B=32, UNITS=64, K=2 (5 Chebyshev terms)
//
// Reference quirk (verified): in _gconv the inner loop reassigns x0, so the
// second support's terms are built on the FIRST support's x1:
//   xs = [x0, S0@x0, 2*S0@xs1 - x0, S1@xs1, 2*S1@xs3 - xs1]
//
// Pipeline:
//   1. rowsum/colsum of adj -> inverse factors
//   2. S0[i,j]=adj[j,i]*invrow[j], S1[i,j]=adj[i,j]*invcol[j]  (tiled transpose)
//   3. per layer:
//        pack x0 (layout [n][f][b]); 4x SGEMM diffusion (gate, full width)
//        W-GEMM gate -> sigmoid -> u stored, r*hx overwrites x0 hx-columns
//        4x SGEMM diffusion (candidate, hx columns only; inp columns reused —
//        diffusion is per-column linear, so gate-phase inp columns are valid)
//        W-GEMM cand -> tanh -> h = u*hx + (1-u)*c -> d_out
//   4. projection h1 @ w_proj + b_proj -> out
// ----------------------------------------------------------------------------

#define NN   2048
#define BB   32
#define UU   64
static const size_t BUFSZ = 2048ull * 4096ull;   // per-term buffer (max FB = 128*32)

__device__ float g_S0[2048ull * 2048ull];
__device__ float g_S1[2048ull * 2048ull];
__device__ float g_inv_row[NN];
__device__ float g_inv_col[NN];
__device__ float g_X[5ull * 2048ull * 4096ull];  // 5 diffusion buffers, layout [n][f][b]
__device__ float g_U[2048ull * 64ull * 32ull];   // u gate, layout [n][u][b]

// ------------------------------ support prep --------------------------------

__global__ void rowsum_kernel(const float* __restrict__ adj) {
    int row = blockIdx.x, tid = threadIdx.x;
    float s = 0.f;
    for (int k = tid; k < NN; k += 256) s += adj[(size_t)row * NN + k];
    __shared__ float sm[256];
    sm[tid] = s; __syncthreads();
    for (int o = 128; o > 0; o >>= 1) { if (tid < o) sm[tid] += sm[tid + o]; __syncthreads(); }
    if (tid == 0) g_inv_row[row] = 1.0f / fmaxf(sm[0], 1e-8f);
}

__global__ void colsum_kernel(const float* __restrict__ adj) {
    int j = blockIdx.x * 32 + threadIdx.x;
    int ty = threadIdx.y;
    float s = 0.f;
    for (int k = ty; k < NN; k += 8) s += adj[(size_t)k * NN + j];
    __shared__ float sm[8][32];
    sm[ty][threadIdx.x] = s; __syncthreads();
    if (ty == 0) {
        float t = 0.f;
        #pragma unroll
        for (int r = 0; r < 8; r++) t += sm[r][threadIdx.x];
        g_inv_col[j] = 1.0f / fmaxf(t, 1e-8f);
    }
}

// block (32,8), grid (64,64): 32x32 tile transpose + scale
__global__ void build_supports(const float* __restrict__ adj) {
    __shared__ float t[32][33];
    int tx = threadIdx.x, ty = threadIdx.y;
    int j0 = blockIdx.x * 32, i0 = blockIdx.y * 32;
    #pragma unroll
    for (int s = 0; s < 4; s++) {
        int r = ty + s * 8;
        t[r][tx] = adj[(size_t)(i0 + r) * NN + j0 + tx];
    }
    __syncthreads();
    float icol = g_inv_col[j0 + tx];
    float irow = g_inv_row[i0 + tx];
    #pragma unroll
    for (int s = 0; s < 4; s++) {
        int r = ty + s * 8;
        // S1[i,j] = adj[i,j] * invcol[j]
        g_S1[(size_t)(i0 + r) * NN + j0 + tx] = t[r][tx] * icol;
        // S0[i,j] = adj[j,i] * invrow[j]; this tile: i in [j0,j0+32), j in [i0,i0+32)
        g_S0[(size_t)(j0 + r) * NN + i0 + tx] = t[tx][r] * irow;
    }
}

// ------------------------------ x0 packing ----------------------------------

__global__ void pack0_kernel(const float* __restrict__ inp, const float* __restrict__ hx0) {
    int n = blockIdx.x;
    for (int idx = threadIdx.x; idx < 65 * 32; idx += 256) {
        int f = idx >> 5, b = idx & 31;
        float v = (f == 0) ? inp[(size_t)b * NN + n]
                           : hx0[(size_t)b * (NN * UU) + (size_t)n * UU + (f - 1)];
        g_X[(size_t)n * 2080 + idx] = v;
    }
}

__global__ void pack1_kernel(const float* __restrict__ h0, const float* __restrict__ hx1) {
    int n = blockIdx.x;
    for (int idx = threadIdx.x; idx < 128 * 32; idx += 256) {
        int f = idx >> 5, b = idx & 31;
        float v = (f < 64) ? h0[(size_t)b * (NN * UU) + (size_t)n * UU + f]
                           : hx1[(size_t)b * (NN * UU) + (size_t)n * UU + (f - 64)];
        g_X[(size_t)n * 4096 + idx] = v;
    }
}

// --------------------------- diffusion SGEMM --------------------------------
// Y[:, cols] = alpha * (S @ X[:, cols]) + beta * Xprev[:, cols]
// 128x128x16 tile, 8x8 per thread, 256 threads, register prefetch.

__global__ void __launch_bounds__(256)
sgemm_diff(int sSel, int xIdx, int yIdx, int prevIdx,
           int ld, int colOff, int colW, float alpha, float beta)
{
    const float* __restrict__ S  = sSel ? g_S1 : g_S0;
    const float* __restrict__ X  = g_X + (size_t)xIdx * BUFSZ;
    float*       __restrict__ Y  = g_X + (size_t)yIdx * BUFSZ;
    const float* __restrict__ Xp = (prevIdx >= 0) ? (g_X + (size_t)prevIdx * BUFSZ) : nullptr;

    __shared__ float As[16][128];
    __shared__ float Bs[16][128];

    int tid  = threadIdx.x;
    int row0 = blockIdx.y * 128;
    int col0 = colOff + blockIdx.x * 128;
    int colEnd = colOff + colW;
    int tx = tid & 15, ty = tid >> 4;

    int aRow = tid >> 1;         // 0..127
    int aK   = (tid & 1) * 8;    // 0 or 8
    int bRow = tid >> 5;         // 0..7
    int bC   = (tid & 31) * 4;   // 0..124

    const float* aPtr = S + (size_t)(row0 + aRow) * NN + aK;
    const float* bPtr = X + (size_t)bRow * ld + col0 + bC;
    bool bPred = (col0 + bC) < colEnd;
    float4 zero4 = make_float4(0.f, 0.f, 0.f, 0.f);

    float4 a0 = *(const float4*)(aPtr);
    float4 a1 = *(const float4*)(aPtr + 4);
    float4 b0 = bPred ? *(const float4*)(bPtr) : zero4;
    float4 b1 = bPred ? *(const float4*)(bPtr + (size_t)8 * ld) : zero4;

    float acc[8][8];
    #pragma unroll
    for (int i = 0; i < 8; i++)
        #pragma unroll
        for (int j = 0; j < 8; j++) acc[i][j] = 0.f;

    for (int k0 = 0; k0 < NN; k0 += 16) {
        As[aK + 0][aRow] = a0.x; As[aK + 1][aRow] = a0.y;
        As[aK + 2][aRow] = a0.z; As[aK + 3][aRow] = a0.w;
        As[aK + 4][aRow] = a1.x; As[aK + 5][aRow] = a1.y;
        As[aK + 6][aRow] = a1.z; As[aK + 7][aRow] = a1.w;
        *(float4*)&Bs[bRow][bC]     = b0;
        *(float4*)&Bs[bRow + 8][bC] = b1;
        __syncthreads();

        if (k0 + 16 < NN) {
            a0 = *(const float4*)(aPtr + k0 + 16);
            a1 = *(const float4*)(aPtr + k0 + 20);
            b0 = bPred ? *(const float4*)(bPtr + (size_t)(k0 + 16) * ld) : zero4;
            b1 = bPred ? *(const float4*)(bPtr + (size_t)(k0 + 24) * ld) : zero4;
        }

        #pragma unroll
        for (int kk = 0; kk < 16; kk++) {
            float ra[8], rb[8];
            *(float4*)&ra[0] = *(const float4*)&As[kk][ty * 8];
            *(float4*)&ra[4] = *(const float4*)&As[kk][ty * 8 + 4];
            *(float4*)&rb[0] = *(const float4*)&Bs[kk][tx * 8];
            *(float4*)&rb[4] = *(const float4*)&Bs[kk][tx * 8 + 4];
            #pragma unroll
            for (int i = 0; i < 8; i++)
                #pragma unroll
                for (int j = 0; j < 8; j++)
                    acc[i][j] = fmaf(ra[i], rb[j], acc[i][j]);
        }
        __syncthreads();
    }

    #pragma unroll
    for (int i = 0; i < 8; i++) {
        size_t r = (size_t)(row0 + ty * 8 + i);
        #pragma unroll
        for (int j4 = 0; j4 < 8; j4 += 4) {
            int c = col0 + tx * 8 + j4;
            if (c < colEnd) {
                float4 v;
                v.x = alpha * acc[i][j4 + 0];
                v.y = alpha * acc[i][j4 + 1];
                v.z = alpha * acc[i][j4 + 2];
                v.w = alpha * acc[i][j4 + 3];
                if (Xp) {
                    float4 p = *(const float4*)(Xp + r * ld + c);
                    v.x += beta * p.x; v.y += beta * p.y;
                    v.z += beta * p.z; v.w += beta * p.w;
                }
                *(float4*)(Y + r * ld + c) = v;
            }
        }
    }
}

// ------------------------------ W-GEMM --------------------------------------
// out[b,n,o] = act( bias[o] + sum_{f,m} X_m[n,f,b] * W[f*5+m, o] )
// MODE 0 (gate): sigmoid; o<64 -> write r*hx into x0 buffer (cand hx columns),
//                o>=64 -> store u into g_U.
// MODE 1 (cand): tanh; h = u*hx + (1-u)*c -> hout.
// One CTA per n; 256 threads: b = tid&31, o-group = tid>>5 (OW = O/8 each).

template <int O, int MODE>
__global__ void __launch_bounds__(256)
wgemm_kernel(int F, int ld,
             const float* __restrict__ W, const float* __restrict__ bias,
             const float* __restrict__ hx, float* __restrict__ hout, int FinB)
{
    const int OW = O / 8;
    int n   = blockIdx.x;
    int tid = threadIdx.x;
    int b   = tid & 31;
    int o0  = (tid >> 5) * OW;

    __shared__ float xs[5][32][32];

    float acc[OW];
    #pragma unroll
    for (int j = 0; j < OW; j++) acc[j] = 0.f;

    for (int fc = 0; fc < F; fc += 32) {
        int fcnt = min(32, F - fc);
        __syncthreads();
        #pragma unroll
        for (int m = 0; m < 5; m++) {
            const float* src = g_X + (size_t)m * BUFSZ + (size_t)n * ld + (size_t)fc * 32;
            for (int idx = tid; idx < fcnt * 32; idx += 256)
                xs[m][idx >> 5][idx & 31] = src[idx];
        }
        __syncthreads();

        for (int ff = 0; ff < fcnt; ff++) {
            int wr0 = (fc + ff) * 5;
            #pragma unroll
            for (int m = 0; m < 5; m++) {
                float xv = xs[m][ff][b];
                const float4* wrow = (const float4*)(W + (size_t)(wr0 + m) * O + o0);
                #pragma unroll
                for (int j4 = 0; j4 < OW / 4; j4++) {
                    float4 wv = wrow[j4];
                    acc[j4 * 4 + 0] = fmaf(xv, wv.x, acc[j4 * 4 + 0]);
                    acc[j4 * 4 + 1] = fmaf(xv, wv.y, acc[j4 * 4 + 1]);
                    acc[j4 * 4 + 2] = fmaf(xv, wv.z, acc[j4 * 4 + 2]);
                    acc[j4 * 4 + 3] = fmaf(xv, wv.w, acc[j4 * 4 + 3]);
                }
            }
        }
    }

    if (MODE == 0) {
        // gate: sigmoid -> r (o<64) writes r*hx into cand x0, u (o>=64) -> g_U
        #pragma unroll
        for (int j = 0; j < OW; j++) {
            int o = o0 + j;
            float v = 1.0f / (1.0f + __expf(-(acc[j] + bias[o])));
            if (o < 64) {
                float h = hx[(size_t)b * (NN * UU) + (size_t)n * UU + o];
                g_X[(size_t)n * ld + (size_t)(FinB + o * 32) + b] = v * h;
            } else {
                g_U[((size_t)n * 64 + (o - 64)) * 32 + b] = v;
            }
        }
    } else {
        // cand: tanh, h = u*hx + (1-u)*c
        #pragma unroll
        for (int j = 0; j < OW; j++) {
            int o = o0 + j;
            float c  = tanhf(acc[j] + bias[o]);
            float u  = g_U[((size_t)n * 64 + o) * 32 + b];
            float hp = hx[(size_t)b * (NN * UU) + (size_t)n * UU + o];
            hout[(size_t)b * (NN * UU) + (size_t)n * UU + o] = u * hp + (1.0f - u) * c;
        }
    }
}

// ------------------------------ projection ----------------------------------

__global__ void proj_kernel(const float* __restrict__ h1, const float* __restrict__ wp,
                            const float* __restrict__ bp, float* __restrict__ out)
{
    int warp = (blockIdx.x * blockDim.x + threadIdx.x) >> 5;
    int lane = threadIdx.x & 31;
    if (warp >= BB * NN) return;
    int b = warp >> 11, n = warp & (NN - 1);
    const float* hr = h1 + (size_t)b * (NN * UU) + (size_t)n * UU;
    float s = hr[lane] * wp[lane] + hr[lane + 32] * wp[lane + 32];
    #pragma unroll
    for (int o = 16; o > 0; o >>= 1) s += __shfl_down_sync(0xffffffffu, s, o);
    if (lane == 0) out[(size_t)b * NN + n] = s + bp[0];
}

// ------------------------------ driver --------------------------------------

// Correct Chebyshev chain per reference (x0 mutates between supports):
//   buf1 = S0 @ buf0
//   buf2 = 2*S0 @ buf1 - buf0
//   buf3 = S1 @ buf1            (input is buf1, not buf0!)
//   buf4 = 2*S1 @ buf3 - buf1   (subtract buf1, not buf0!)
static void run_diffusion(int colOff, int colW, int ld) {
    dim3 grid((colW + 127) / 128, NN / 128);
    sgemm_diff<<<grid, 256>>>(0, 0, 1, -1, ld, colOff, colW, 1.0f,  0.0f);  // buf1
    sgemm_diff<<<grid, 256>>>(0, 1, 2,  0, ld, colOff, colW, 2.0f, -1.0f);  // buf2
    sgemm_diff<<<grid, 256>>>(1, 1, 3, -1, ld, colOff, colW, 1.0f,  0.0f);  // buf3 = S1@buf1
    sgemm_diff<<<grid, 256>>>(1, 3, 4,  1, ld, colOff, colW, 2.0f, -1.0f);  // buf4 = 2*S1@buf3 - buf1
}

extern "C" void kernel_launch(void* const* d_in, const int* in_sizes, int n_in,
                              void* d_out, int out_size)
{
    const float* inputs = (const float*)d_in[0];
    const float* hidden = (const float*)d_in[1];
    const float* adj    = (const float*)d_in[2];
    const float* wg0    = (const float*)d_in[3];
    const float* bg0    = (const float*)d_in[4];
    const float* wc0    = (const float*)d_in[5];
    const float* bc0    = (const float*)d_in[6];
    const float* wg1    = (const float*)d_in[7];
    const float* bg1    = (const float*)d_in[8];
    const float* wc1    = (const float*)d_in[9];
    const float* bc1    = (const float*)d_in[10];
    const float* wproj  = (const float*)d_in[11];
    const float* bproj  = (const float*)d_in[12];

    float* out = (float*)d_out;                       // (B, N)
    float* h0  = out + (size_t)BB * NN;               // (B, N*U)
    float* h1  = h0 + (size_t)BB * NN * UU;           // (B, N*U)
    const float* hx0 = hidden;
    const float* hx1 = hidden + (size_t)BB * NN * UU;

    // supports
    rowsum_kernel<<<NN, 256>>>(adj);
    colsum_kernel<<<NN / 32, dim3(32, 8)>>>(adj);
    build_supports<<<dim3(NN / 32, NN / 32), dim3(32, 8)>>>(adj);

    // ---- layer 0 (F = 1+64 = 65, ld = 2080) ----
    pack0_kernel<<<NN, 256>>>(inputs, hx0);
    run_diffusion(0, 2080, 2080);                                         // gate: full width
    wgemm_kernel<128, 0><<<NN, 256>>>(65, 2080, wg0, bg0, hx0, nullptr, 32);
    run_diffusion(32, 2048, 2080);                                        // cand: hx cols only
    wgemm_kernel<64, 1><<<NN, 256>>>(65, 2080, wc0, bc0, hx0, h0, 0);

    // ---- layer 1 (F = 64+64 = 128, ld = 4096) ----
    pack1_kernel<<<NN, 256>>>(h0, hx1);
    run_diffusion(0, 4096, 4096);
    wgemm_kernel<128, 0><<<NN, 256>>>(128, 4096, wg1, bg1, hx1, nullptr, 2048);
    run_diffusion(2048, 2048, 4096);
    wgemm_kernel<64, 1><<<NN, 256>>>(128, 4096, wc1, bc1, hx1, h1, 0);

    // projection
    proj_kernel<<<(BB * NN) / 8, 256>>>(h1, wproj, bproj, out);
}

// round 9
// speedup vs baseline: 2.7986x; 2.7986x over previous
#include <cuda_runtime.h>
#include <cuda_bf16.h>
#include <cstdint>

// ----------------------------------------------------------------------------
// DCRNN decoder cell (2 layers), N=2048, B=32, UNITS=64, 5 Chebyshev terms.
// Diffusion GEMMs on mma.sync bf16 tensor cores (sm_80 baseline ISA — the
// harness toolchain lowers via .target sm_103 which rejects all sm_103a-gated
// tcgen05 features). Everything else fp32.
// Chain (reference quirk — x0 mutates between supports):
//   buf1 = S0@buf0 ; buf2 = 2*S0@buf1 - buf0 ; buf3 = S1@buf1 ; buf4 = 2*S1@buf3 - buf1
// ----------------------------------------------------------------------------

#define NN   2048
#define BB   32
#define UU   64
static const size_t BUFSZ = 2048ull * 4096ull;   // fp32 per-term buffer
static const size_t MIRSZ = 2048ull * 4096ull;   // bf16 mirror buffer

__device__ __nv_bfloat16 g_S0h[2048ull * 2048ull];
__device__ __nv_bfloat16 g_S1h[2048ull * 2048ull];
__device__ float g_inv_row[NN];
__device__ float g_inv_col[NN];
__device__ float g_X[5ull * 2048ull * 4096ull];          // fp32 term buffers [n][f][b]
__device__ __nv_bfloat16 g_Xh[3ull * 2048ull * 4096ull]; // bf16 mirrors: 0=buf0,1=buf1,2=buf3
__device__ float g_U[2048ull * 64ull * 32ull];

// ----------------------------- PTX helpers ----------------------------------

__device__ __forceinline__ uint32_t smem_u32(const void* p) {
    uint32_t r;
    asm("{ .reg .u64 t; cvta.to.shared.u64 t, %1; cvt.u32.u64 %0, t; }" : "=r"(r) : "l"(p));
    return r;
}

__device__ __forceinline__ void cp16(uint32_t sm, const void* g, int srcsize) {
    asm volatile("cp.async.cg.shared.global [%0], [%1], 16, %2;"
                 :: "r"(sm), "l"(g), "r"(srcsize) : "memory");
}

__device__ __forceinline__ void ldmA(uint32_t* r, uint32_t addr) {
    asm volatile("ldmatrix.sync.aligned.m8n8.x4.shared.b16 {%0,%1,%2,%3}, [%4];"
                 : "=r"(r[0]), "=r"(r[1]), "=r"(r[2]), "=r"(r[3]) : "r"(addr));
}

__device__ __forceinline__ void ldmBT(uint32_t* r, uint32_t addr) {
    asm volatile("ldmatrix.sync.aligned.m8n8.x4.trans.shared.b16 {%0,%1,%2,%3}, [%4];"
                 : "=r"(r[0]), "=r"(r[1]), "=r"(r[2]), "=r"(r[3]) : "r"(addr));
}

__device__ __forceinline__ void mma16816(float* c, const uint32_t* a, const uint32_t* b) {
    asm volatile(
        "mma.sync.aligned.m16n8k16.row.col.f32.bf16.bf16.f32 "
        "{%0,%1,%2,%3},{%4,%5,%6,%7},{%8,%9},{%0,%1,%2,%3};"
        : "+f"(c[0]), "+f"(c[1]), "+f"(c[2]), "+f"(c[3])
        : "r"(a[0]), "r"(a[1]), "r"(a[2]), "r"(a[3]), "r"(b[0]), "r"(b[1]));
}

// ------------------------------ support prep --------------------------------

__global__ void rowsum_kernel(const float* __restrict__ adj) {
    int row = blockIdx.x, tid = threadIdx.x;
    float s = 0.f;
    for (int k = tid; k < NN; k += 256) s += adj[(size_t)row * NN + k];
    __shared__ float sm[256];
    sm[tid] = s; __syncthreads();
    for (int o = 128; o > 0; o >>= 1) { if (tid < o) sm[tid] += sm[tid + o]; __syncthreads(); }
    if (tid == 0) g_inv_row[row] = 1.0f / fmaxf(sm[0], 1e-8f);
}

__global__ void colsum_kernel(const float* __restrict__ adj) {
    int j = blockIdx.x * 32 + threadIdx.x;
    int ty = threadIdx.y;
    float s = 0.f;
    for (int k = ty; k < NN; k += 8) s += adj[(size_t)k * NN + j];
    __shared__ float sm[8][32];
    sm[ty][threadIdx.x] = s; __syncthreads();
    if (ty == 0) {
        float t = 0.f;
        #pragma unroll
        for (int r = 0; r < 8; r++) t += sm[r][threadIdx.x];
        g_inv_col[j] = 1.0f / fmaxf(t, 1e-8f);
    }
}

// block (32,8), grid (64,64): 32x32 tile transpose + scale, write bf16 supports
__global__ void build_supports(const float* __restrict__ adj) {
    __shared__ float t[32][33];
    int tx = threadIdx.x, ty = threadIdx.y;
    int j0 = blockIdx.x * 32, i0 = blockIdx.y * 32;
    #pragma unroll
    for (int s = 0; s < 4; s++) {
        int r = ty + s * 8;
        t[r][tx] = adj[(size_t)(i0 + r) * NN + j0 + tx];
    }
    __syncthreads();
    float icol = g_inv_col[j0 + tx];
    float irow = g_inv_row[i0 + tx];
    #pragma unroll
    for (int s = 0; s < 4; s++) {
        int r = ty + s * 8;
        g_S1h[(size_t)(i0 + r) * NN + j0 + tx] = __float2bfloat16(t[r][tx] * icol);
        g_S0h[(size_t)(j0 + r) * NN + i0 + tx] = __float2bfloat16(t[tx][r] * irow);
    }
}

// ------------------------------ x0 packing ----------------------------------

__global__ void pack0_kernel(const float* __restrict__ inp, const float* __restrict__ hx0) {
    int n = blockIdx.x;
    for (int idx = threadIdx.x; idx < 65 * 32; idx += 256) {
        int f = idx >> 5, b = idx & 31;
        float v = (f == 0) ? inp[(size_t)b * NN + n]
                           : hx0[(size_t)b * (NN * UU) + (size_t)n * UU + (f - 1)];
        g_X[(size_t)n * 2080 + idx] = v;
        g_Xh[(size_t)n * 2112 + idx] = __float2bfloat16(v);
    }
}

__global__ void pack1_kernel(const float* __restrict__ h0, const float* __restrict__ hx1) {
    int n = blockIdx.x;
    for (int idx = threadIdx.x; idx < 128 * 32; idx += 256) {
        int f = idx >> 5, b = idx & 31;
        float v = (f < 64) ? h0[(size_t)b * (NN * UU) + (size_t)n * UU + f]
                           : hx1[(size_t)b * (NN * UU) + (size_t)n * UU + (f - 64)];
        g_X[(size_t)n * 4096 + idx] = v;
        g_Xh[(size_t)n * 4096 + idx] = __float2bfloat16(v);
    }
}

// ------------------- diffusion GEMM (mma.sync bf16) -------------------------
// Y[:,cols] = alpha*(S @ X[:,cols]) + beta*Xprev[:,cols]; optional bf16 mirror.
// CTA 128x128, k-chunk 32, double-buffered cp.async; 8 warps (2M x 4N),
// warp tile 64x32 via m16n8k16.

#define AST 40    // A smem row stride (bf16 elems) = 80B  -> conflict-free ldmatrix
#define BST 136   // B smem row stride (bf16 elems) = 272B -> conflict-free ldmatrix
#define ASB (128 * AST * 2)   // bytes per A stage
#define BSB (32 * BST * 2)    // bytes per B stage

__global__ void __launch_bounds__(256)
diff_mma(int sSel, int xhIdx, int yIdx, int prevIdx, int yhIdx,
         int ld, int ldh, int colOff, int colEnd, float alpha, float beta)
{
    __shared__ __nv_bfloat16 As[2][128 * AST];
    __shared__ __nv_bfloat16 Bs[2][32 * BST];

    const __nv_bfloat16* __restrict__ S  = sSel ? g_S1h : g_S0h;
    const __nv_bfloat16* __restrict__ Xh = g_Xh + (size_t)xhIdx * MIRSZ;
    float*       __restrict__ Y  = g_X + (size_t)yIdx * BUFSZ;
    const float* __restrict__ Xp = (prevIdx >= 0) ? (g_X + (size_t)prevIdx * BUFSZ) : nullptr;
    __nv_bfloat16* __restrict__ Yh = (yhIdx >= 0) ? (g_Xh + (size_t)yhIdx * MIRSZ) : nullptr;

    const int tid  = threadIdx.x;
    const int row0 = blockIdx.y * 128;
    const int col0 = colOff + blockIdx.x * 128;

    const int wid = tid >> 5, lane = tid & 31;
    const int wm = (wid & 1) * 64;          // warp M offset
    const int wn = (wid >> 1) * 32;         // warp N offset

    // ldmatrix lane addressing
    const int aR = (lane & 7) + ((lane >> 3) & 1) * 8;   // A: row within 16-tile
    const int aC = (lane >> 4) * 8;                      // A: k offset 0/8
    const int bR = ((lane >> 3) & 1) * 8 + (lane & 7);   // B: k row within 16
    const int bC = (lane >> 4) * 8;                      // B: n offset 0/8

    const uint32_t asB = smem_u32(As);
    const uint32_t bsB = smem_u32(Bs);

    float acc[4][4][4];
    #pragma unroll
    for (int mi = 0; mi < 4; mi++)
        #pragma unroll
        for (int ni = 0; ni < 4; ni++)
            #pragma unroll
            for (int q = 0; q < 4; q++) acc[mi][ni][q] = 0.f;

    // stage loader: k-chunk i -> buffer i&1
    auto LOAD = [&](int i) {
        int k0 = i * 32, s = i & 1;
        #pragma unroll
        for (int t = 0; t < 2; t++) {
            int aIdx = t * 256 + tid;           // 512 uint4 for A (128 rows x 4)
            int r = aIdx >> 2, kq = aIdx & 3;
            cp16(asB + s * ASB + (uint32_t)(r * AST + kq * 8) * 2,
                 S + (size_t)(row0 + r) * NN + k0 + kq * 8, 16);
        }
        #pragma unroll
        for (int t = 0; t < 2; t++) {
            int bIdx = t * 256 + tid;           // 512 uint4 for B (32 rows x 16)
            int kr = bIdx >> 4, nq = bIdx & 15;
            int c = col0 + nq * 8;
            cp16(bsB + s * BSB + (uint32_t)(kr * BST + nq * 8) * 2,
                 Xh + (size_t)(k0 + kr) * ldh + c, (c < colEnd) ? 16 : 0);
        }
    };

    LOAD(0);
    asm volatile("cp.async.commit_group;" ::: "memory");

    for (int i = 0; i < 64; i++) {
        if (i + 1 < 64) LOAD(i + 1);
        asm volatile("cp.async.commit_group;" ::: "memory");
        asm volatile("cp.async.wait_group 1;" ::: "memory");
        __syncthreads();

        const int s = i & 1;
        #pragma unroll
        for (int kc = 0; kc < 32; kc += 16) {
            uint32_t af[4][4], bf[2][4];
            #pragma unroll
            for (int mi = 0; mi < 4; mi++)
                ldmA(af[mi], asB + s * ASB +
                     (uint32_t)((wm + mi * 16 + aR) * AST + kc + aC) * 2);
            #pragma unroll
            for (int np = 0; np < 2; np++)
                ldmBT(bf[np], bsB + s * BSB +
                      (uint32_t)((kc + bR) * BST + wn + np * 16 + bC) * 2);
            #pragma unroll
            for (int mi = 0; mi < 4; mi++)
                #pragma unroll
                for (int ni = 0; ni < 4; ni++)
                    mma16816(acc[mi][ni], af[mi], &bf[ni >> 1][(ni & 1) * 2]);
        }
        __syncthreads();
    }

    // epilogue: C frag -> rows {g, g+8}, cols {2tig, 2tig+1}
    const int g = lane >> 2, tig = lane & 3;
    #pragma unroll
    for (int mi = 0; mi < 4; mi++) {
        #pragma unroll
        for (int half = 0; half < 2; half++) {
            int r = row0 + wm + mi * 16 + g + half * 8;
            float* yRow = Y + (size_t)r * ld;
            const float* pRow = Xp ? (Xp + (size_t)r * ld) : nullptr;
            __nv_bfloat16* hRow = Yh ? (Yh + (size_t)r * ldh) : nullptr;
            #pragma unroll
            for (int ni = 0; ni < 4; ni++) {
                int c = col0 + wn + ni * 8 + tig * 2;
                if (c < colEnd) {
                    float vx = alpha * acc[mi][ni][half * 2 + 0];
                    float vy = alpha * acc[mi][ni][half * 2 + 1];
                    if (pRow) {
                        float2 p = *(const float2*)(pRow + c);
                        vx = fmaf(beta, p.x, vx);
                        vy = fmaf(beta, p.y, vy);
                    }
                    *(float2*)(yRow + c) = make_float2(vx, vy);
                    if (hRow)
                        *(__nv_bfloat162*)(hRow + c) = __floats2bfloat162_rn(vx, vy);
                }
            }
        }
    }
}

// ------------------------------ W-GEMM --------------------------------------

template <int O, int MODE>
__global__ void __launch_bounds__(256)
wgemm_kernel(int F, int ld, int mldh,
             const float* __restrict__ W, const float* __restrict__ bias,
             const float* __restrict__ hx, float* __restrict__ hout, int FinB)
{
    const int OW = O / 8;
    int n   = blockIdx.x;
    int tid = threadIdx.x;
    int b   = tid & 31;
    int o0  = (tid >> 5) * OW;

    __shared__ float xs[5][32][32];

    float acc[OW];
    #pragma unroll
    for (int j = 0; j < OW; j++) acc[j] = 0.f;

    for (int fc = 0; fc < F; fc += 32) {
        int fcnt = min(32, F - fc);
        __syncthreads();
        #pragma unroll
        for (int m = 0; m < 5; m++) {
            const float* src = g_X + (size_t)m * BUFSZ + (size_t)n * ld + (size_t)fc * 32;
            for (int idx = tid; idx < fcnt * 32; idx += 256)
                xs[m][idx >> 5][idx & 31] = src[idx];
        }
        __syncthreads();

        for (int ff = 0; ff < fcnt; ff++) {
            int wr0 = (fc + ff) * 5;
            #pragma unroll
            for (int m = 0; m < 5; m++) {
                float xv = xs[m][ff][b];
                const float4* wrow = (const float4*)(W + (size_t)(wr0 + m) * O + o0);
                #pragma unroll
                for (int j4 = 0; j4 < OW / 4; j4++) {
                    float4 wv = wrow[j4];
                    acc[j4 * 4 + 0] = fmaf(xv, wv.x, acc[j4 * 4 + 0]);
                    acc[j4 * 4 + 1] = fmaf(xv, wv.y, acc[j4 * 4 + 1]);
                    acc[j4 * 4 + 2] = fmaf(xv, wv.z, acc[j4 * 4 + 2]);
                    acc[j4 * 4 + 3] = fmaf(xv, wv.w, acc[j4 * 4 + 3]);
                }
            }
        }
    }

    if (MODE == 0) {
        #pragma unroll
        for (int j = 0; j < OW; j++) {
            int o = o0 + j;
            float v = 1.0f / (1.0f + __expf(-(acc[j] + bias[o])));
            if (o < 64) {
                float h = hx[(size_t)b * (NN * UU) + (size_t)n * UU + o];
                float rh = v * h;
                g_X[(size_t)n * ld + (size_t)(FinB + o * 32) + b] = rh;
                g_Xh[(size_t)n * mldh + (size_t)(FinB + o * 32) + b] = __float2bfloat16(rh);
            } else {
                g_U[((size_t)n * 64 + (o - 64)) * 32 + b] = v;
            }
        }
    } else {
        #pragma unroll
        for (int j = 0; j < OW; j++) {
            int o = o0 + j;
            float c  = tanhf(acc[j] + bias[o]);
            float u  = g_U[((size_t)n * 64 + o) * 32 + b];
            float hp = hx[(size_t)b * (NN * UU) + (size_t)n * UU + o];
            hout[(size_t)b * (NN * UU) + (size_t)n * UU + o] = u * hp + (1.0f - u) * c;
        }
    }
}

// ------------------------------ projection ----------------------------------

__global__ void proj_kernel(const float* __restrict__ h1, const float* __restrict__ wp,
                            const float* __restrict__ bp, float* __restrict__ out)
{
    int warp = (blockIdx.x * blockDim.x + threadIdx.x) >> 5;
    int lane = threadIdx.x & 31;
    if (warp >= BB * NN) return;
    int b = warp >> 11, n = warp & (NN - 1);
    const float* hr = h1 + (size_t)b * (NN * UU) + (size_t)n * UU;
    float s = hr[lane] * wp[lane] + hr[lane + 32] * wp[lane + 32];
    #pragma unroll
    for (int o = 16; o > 0; o >>= 1) s += __shfl_down_sync(0xffffffffu, s, o);
    if (lane == 0) out[(size_t)b * NN + n] = s + bp[0];
}

// ------------------------------ driver --------------------------------------

static void run_diffusion(int colOff, int colW, int ld, int ldh) {
    int tiles = (colW + 127) / 128;
    dim3 g(tiles, 16);
    int ce = colOff + colW;
    diff_mma<<<g, 256>>>(0, 0, 1, -1,  1, ld, ldh, colOff, ce, 1.0f,  0.0f); // buf1 = S0@buf0
    diff_mma<<<g, 256>>>(0, 1, 2,  0, -1, ld, ldh, colOff, ce, 2.0f, -1.0f); // buf2 = 2*S0@buf1 - buf0
    diff_mma<<<g, 256>>>(1, 1, 3, -1,  2, ld, ldh, colOff, ce, 1.0f,  0.0f); // buf3 = S1@buf1
    diff_mma<<<g, 256>>>(1, 2, 4,  1, -1, ld, ldh, colOff, ce, 2.0f, -1.0f); // buf4 = 2*S1@buf3 - buf1
}

extern "C" void kernel_launch(void* const* d_in, const int* in_sizes, int n_in,
                              void* d_out, int out_size)
{
    const float* inputs = (const float*)d_in[0];
    const float* hidden = (const float*)d_in[1];
    const float* adj    = (const float*)d_in[2];
    const float* wg0    = (const float*)d_in[3];
    const float* bg0    = (const float*)d_in[4];
    const float* wc0    = (const float*)d_in[5];
    const float* bc0    = (const float*)d_in[6];
    const float* wg1    = (const float*)d_in[7];
    const float* bg1    = (const float*)d_in[8];
    const float* wc1    = (const float*)d_in[9];
    const float* bc1    = (const float*)d_in[10];
    const float* wproj  = (const float*)d_in[11];
    const float* bproj  = (const float*)d_in[12];

    float* out = (float*)d_out;                       // (B, N)
    float* h0  = out + (size_t)BB * NN;               // (B, N*U)
    float* h1  = h0 + (size_t)BB * NN * UU;           // (B, N*U)
    const float* hx0 = hidden;
    const float* hx1 = hidden + (size_t)BB * NN * UU;

    // supports
    rowsum_kernel<<<NN, 256>>>(adj);
    colsum_kernel<<<NN / 32, dim3(32, 8)>>>(adj);
    build_supports<<<dim3(NN / 32, NN / 32), dim3(32, 8)>>>(adj);

    // ---- layer 0 (F = 65, fp32 ld = 2080, bf16 ldh = 2112) ----
    pack0_kernel<<<NN, 256>>>(inputs, hx0);
    run_diffusion(0, 2080, 2080, 2112);                                   // gate: full width
    wgemm_kernel<128, 0><<<NN, 256>>>(65, 2080, 2112, wg0, bg0, hx0, nullptr, 32);
    run_diffusion(32, 2048, 2080, 2112);                                  // cand: hx cols only
    wgemm_kernel<64, 1><<<NN, 256>>>(65, 2080, 0, wc0, bc0, hx0, h0, 0);

    // ---- layer 1 (F = 128, ld = ldh = 4096) ----
    pack1_kernel<<<NN, 256>>>(h0, hx1);
    run_diffusion(0, 4096, 4096, 4096);
    wgemm_kernel<128, 0><<<NN, 256>>>(128, 4096, 4096, wg1, bg1, hx1, nullptr, 2048);
    run_diffusion(2048, 2048, 4096, 4096);
    wgemm_kernel<64, 1><<<NN, 256>>>(128, 4096, 0, wc1, bc1, hx1, h1, 0);

    // projection
    proj_kernel<<<(BB * NN) / 8, 256>>>(h1, wproj, bproj, out);
}

// round 10
// speedup vs baseline: 6.4403x; 2.3013x over previous
#include <cuda_runtime.h>
#include <cuda_bf16.h>
#include <cstdint>

// ----------------------------------------------------------------------------
// DCRNN decoder cell (2 layers), N=2048, B=32, UNITS=64, 5 Chebyshev terms.
// Diffusion + W-GEMMs on mma.sync bf16 (sm_80 baseline ISA; tcgen05 is gated
// off by the harness's .target sm_103 lowering).
// Chain (reference quirk — x0 mutates between supports):
//   buf1 = S0@buf0 ; buf2 = 2*S0@buf1 - buf0 ; buf3 = S1@buf1 ; buf4 = 2*S1@buf3 - buf1
// fp32 kept only for buf0/buf1 (the two 'prev' operands); all GEMM inputs are
// bf16 mirrors (all 5 terms).
// ----------------------------------------------------------------------------

#define NN   2048
#define BB   32
#define UU   64
static const size_t BUFSZ = 2048ull * 4096ull;   // fp32 per-term buffer (buf0, buf1)
static const size_t MIRSZ = 2048ull * 4096ull;   // bf16 mirror buffer (buf0..buf4)

__device__ __nv_bfloat16 g_S0h[2048ull * 2048ull];
__device__ __nv_bfloat16 g_S1h[2048ull * 2048ull];
__device__ float g_inv_row[NN];
__device__ float g_inv_col[NN];
__device__ float g_X[2ull * 2048ull * 4096ull];          // fp32: buf0, buf1
__device__ __nv_bfloat16 g_Xh[5ull * 2048ull * 4096ull]; // bf16 mirrors buf0..4
__device__ float g_U[2048ull * 32ull * 64ull];           // u gate, [n][b][o]
__device__ __nv_bfloat16 g_Wr[5ull * 128ull * 128ull];   // reordered bf16 weights

// ----------------------------- PTX helpers ----------------------------------

__device__ __forceinline__ uint32_t smem_u32(const void* p) {
    uint32_t r;
    asm("{ .reg .u64 t; cvta.to.shared.u64 t, %1; cvt.u32.u64 %0, t; }" : "=r"(r) : "l"(p));
    return r;
}

__device__ __forceinline__ void cp16(uint32_t sm, const void* g, int srcsize) {
    asm volatile("cp.async.cg.shared.global [%0], [%1], 16, %2;"
                 :: "r"(sm), "l"(g), "r"(srcsize) : "memory");
}
#define CP_COMMIT() asm volatile("cp.async.commit_group;" ::: "memory")
#define CP_WAIT2()  asm volatile("cp.async.wait_group 2;" ::: "memory")

__device__ __forceinline__ void ldmA(uint32_t* r, uint32_t addr) {
    asm volatile("ldmatrix.sync.aligned.m8n8.x4.shared.b16 {%0,%1,%2,%3}, [%4];"
                 : "=r"(r[0]), "=r"(r[1]), "=r"(r[2]), "=r"(r[3]) : "r"(addr));
}

// x4 transposed ldmatrix: used for B from [k][n] storage AND A from [k][m] storage
__device__ __forceinline__ void ldm4t(uint32_t* r, uint32_t addr) {
    asm volatile("ldmatrix.sync.aligned.m8n8.x4.trans.shared.b16 {%0,%1,%2,%3}, [%4];"
                 : "=r"(r[0]), "=r"(r[1]), "=r"(r[2]), "=r"(r[3]) : "r"(addr));
}

__device__ __forceinline__ void mma16816(float* c, const uint32_t* a, const uint32_t* b) {
    asm volatile(
        "mma.sync.aligned.m16n8k16.row.col.f32.bf16.bf16.f32 "
        "{%0,%1,%2,%3},{%4,%5,%6,%7},{%8,%9},{%0,%1,%2,%3};"
        : "+f"(c[0]), "+f"(c[1]), "+f"(c[2]), "+f"(c[3])
        : "r"(a[0]), "r"(a[1]), "r"(a[2]), "r"(a[3]), "r"(b[0]), "r"(b[1]));
}

// ------------------------------ support prep --------------------------------

__global__ void rowsum_kernel(const float* __restrict__ adj) {
    int row = blockIdx.x, tid = threadIdx.x;
    float s = 0.f;
    for (int k = tid; k < NN; k += 256) s += adj[(size_t)row * NN + k];
    __shared__ float sm[256];
    sm[tid] = s; __syncthreads();
    for (int o = 128; o > 0; o >>= 1) { if (tid < o) sm[tid] += sm[tid + o]; __syncthreads(); }
    if (tid == 0) g_inv_row[row] = 1.0f / fmaxf(sm[0], 1e-8f);
}

__global__ void colsum_kernel(const float* __restrict__ adj) {
    int j = blockIdx.x * 32 + threadIdx.x;
    int ty = threadIdx.y;
    float s = 0.f;
    for (int k = ty; k < NN; k += 8) s += adj[(size_t)k * NN + j];
    __shared__ float sm[8][32];
    sm[ty][threadIdx.x] = s; __syncthreads();
    if (ty == 0) {
        float t = 0.f;
        #pragma unroll
        for (int r = 0; r < 8; r++) t += sm[r][threadIdx.x];
        g_inv_col[j] = 1.0f / fmaxf(t, 1e-8f);
    }
}

__global__ void build_supports(const float* __restrict__ adj) {
    __shared__ float t[32][33];
    int tx = threadIdx.x, ty = threadIdx.y;
    int j0 = blockIdx.x * 32, i0 = blockIdx.y * 32;
    #pragma unroll
    for (int s = 0; s < 4; s++) {
        int r = ty + s * 8;
        t[r][tx] = adj[(size_t)(i0 + r) * NN + j0 + tx];
    }
    __syncthreads();
    float icol = g_inv_col[j0 + tx];
    float irow = g_inv_row[i0 + tx];
    #pragma unroll
    for (int s = 0; s < 4; s++) {
        int r = ty + s * 8;
        g_S1h[(size_t)(i0 + r) * NN + j0 + tx] = __float2bfloat16(t[r][tx] * icol);
        g_S0h[(size_t)(j0 + r) * NN + i0 + tx] = __float2bfloat16(t[tx][r] * irow);
    }
}

// ------------------------------ x0 packing ----------------------------------

__global__ void pack0_kernel(const float* __restrict__ inp, const float* __restrict__ hx0) {
    int n = blockIdx.x;
    for (int idx = threadIdx.x; idx < 65 * 32; idx += 256) {
        int f = idx >> 5, b = idx & 31;
        float v = (f == 0) ? inp[(size_t)b * NN + n]
                           : hx0[(size_t)b * (NN * UU) + (size_t)n * UU + (f - 1)];
        g_X[(size_t)n * 2080 + idx] = v;
        g_Xh[(size_t)n * 2112 + idx] = __float2bfloat16(v);
    }
}

__global__ void pack1_kernel(const float* __restrict__ h0, const float* __restrict__ hx1) {
    int n = blockIdx.x;
    for (int idx = threadIdx.x; idx < 128 * 32; idx += 256) {
        int f = idx >> 5, b = idx & 31;
        float v = (f < 64) ? h0[(size_t)b * (NN * UU) + (size_t)n * UU + f]
                           : hx1[(size_t)b * (NN * UU) + (size_t)n * UU + (f - 64)];
        g_X[(size_t)n * 4096 + idx] = v;
        g_Xh[(size_t)n * 4096 + idx] = __float2bfloat16(v);
    }
}

// ------------------- diffusion GEMM (mma.sync bf16) -------------------------
// mirror_y = bf16(alpha*(S @ Xh[:,cols]) + beta*Xprev[:,cols]); optional fp32 Y.
// CTA 128x128, k-chunk 32, 4-stage cp.async pipeline; 8 warps (2M x 4N).

#define D_AST 40              // A smem row stride (bf16)
#define D_BST 136             // B smem row stride (bf16)
#define D_ASB (128 * D_AST * 2)
#define D_BSB (32 * D_BST * 2)
#define DIFF_SMEM (4 * (D_ASB + D_BSB))   // 75776 bytes

__global__ void __launch_bounds__(256)
diff_mma(int sSel, int xhIdx, int yIdx, int prevIdx, int yhIdx,
         int ld, int ldh, int colOff, int colEnd, float alpha, float beta)
{
    extern __shared__ __nv_bfloat16 dsm[];
    const uint32_t aBase = smem_u32(dsm);
    const uint32_t bBase = aBase + 4 * D_ASB;

    const __nv_bfloat16* __restrict__ S  = sSel ? g_S1h : g_S0h;
    const __nv_bfloat16* __restrict__ Xh = g_Xh + (size_t)xhIdx * MIRSZ;
    float*       __restrict__ Y  = (yIdx >= 0) ? (g_X + (size_t)yIdx * BUFSZ) : nullptr;
    const float* __restrict__ Xp = (prevIdx >= 0) ? (g_X + (size_t)prevIdx * BUFSZ) : nullptr;
    __nv_bfloat16* __restrict__ Yh = g_Xh + (size_t)yhIdx * MIRSZ;

    const int tid  = threadIdx.x;
    const int row0 = blockIdx.y * 128;
    const int col0 = colOff + blockIdx.x * 128;

    const int wid = tid >> 5, lane = tid & 31;
    const int wm = (wid & 1) * 64;
    const int wn = (wid >> 1) * 32;

    const int aR = (lane & 7) + ((lane >> 3) & 1) * 8;
    const int aC = (lane >> 4) * 8;
    const int bR = ((lane >> 3) & 1) * 8 + (lane & 7);
    const int bC = (lane >> 4) * 8;

    float acc[4][4][4];
    #pragma unroll
    for (int mi = 0; mi < 4; mi++)
        #pragma unroll
        for (int ni = 0; ni < 4; ni++)
            #pragma unroll
            for (int q = 0; q < 4; q++) acc[mi][ni][q] = 0.f;

    auto LOAD = [&](int i) {
        const int k0 = i * 32, s = i & 3;
        #pragma unroll
        for (int t = 0; t < 2; t++) {
            int aIdx = t * 256 + tid;
            int r = aIdx >> 2, kq = aIdx & 3;
            cp16(aBase + s * D_ASB + (uint32_t)(r * D_AST + kq * 8) * 2,
                 S + (size_t)(row0 + r) * NN + k0 + kq * 8, 16);
        }
        #pragma unroll
        for (int t = 0; t < 2; t++) {
            int bIdx = t * 256 + tid;
            int kr = bIdx >> 4, nq = bIdx & 15;
            int c = col0 + nq * 8;
            cp16(bBase + s * D_BSB + (uint32_t)(kr * D_BST + nq * 8) * 2,
                 Xh + (size_t)(k0 + kr) * ldh + c, (c < colEnd) ? 16 : 0);
        }
    };

    LOAD(0); CP_COMMIT();
    LOAD(1); CP_COMMIT();
    LOAD(2); CP_COMMIT();

    for (int i = 0; i < 64; i++) {
        CP_WAIT2();
        __syncthreads();
        if (i + 3 < 64) LOAD(i + 3);
        CP_COMMIT();

        const int s = i & 3;
        #pragma unroll
        for (int kc = 0; kc < 32; kc += 16) {
            uint32_t af[4][4], bf[2][4];
            #pragma unroll
            for (int mi = 0; mi < 4; mi++)
                ldmA(af[mi], aBase + s * D_ASB +
                     (uint32_t)((wm + mi * 16 + aR) * D_AST + kc + aC) * 2);
            #pragma unroll
            for (int np = 0; np < 2; np++)
                ldm4t(bf[np], bBase + s * D_BSB +
                      (uint32_t)((kc + bR) * D_BST + wn + np * 16 + bC) * 2);
            #pragma unroll
            for (int mi = 0; mi < 4; mi++)
                #pragma unroll
                for (int ni = 0; ni < 4; ni++)
                    mma16816(acc[mi][ni], af[mi], &bf[ni >> 1][(ni & 1) * 2]);
        }
        __syncthreads();
    }

    const int g = lane >> 2, t2 = (lane & 3) * 2;
    #pragma unroll
    for (int mi = 0; mi < 4; mi++) {
        #pragma unroll
        for (int half = 0; half < 2; half++) {
            int r = row0 + wm + mi * 16 + g + half * 8;
            float* yRow = Y ? (Y + (size_t)r * ld) : nullptr;
            const float* pRow = Xp ? (Xp + (size_t)r * ld) : nullptr;
            __nv_bfloat16* hRow = Yh + (size_t)r * ldh;
            #pragma unroll
            for (int ni = 0; ni < 4; ni++) {
                int c = col0 + wn + ni * 8 + t2;
                if (c < colEnd) {
                    float vx = alpha * acc[mi][ni][half * 2 + 0];
                    float vy = alpha * acc[mi][ni][half * 2 + 1];
                    if (pRow) {
                        float2 p = *(const float2*)(pRow + c);
                        vx = fmaf(beta, p.x, vx);
                        vy = fmaf(beta, p.y, vy);
                    }
                    if (yRow) *(float2*)(yRow + c) = make_float2(vx, vy);
                    *(__nv_bfloat162*)(hRow + c) = __floats2bfloat162_rn(vx, vy);
                }
            }
        }
    }
}

// ----------------------- weight reorder (fp32 -> bf16) ----------------------
// g_Wr[m][fp][o] = bf16(W[f*5+m][o]) for f<F else 0.

__global__ void wprep_kernel(const float* __restrict__ W, int F, int Fp, int O) {
    int idx = blockIdx.x * 256 + threadIdx.x;
    if (idx >= 5 * Fp * O) return;
    int o = idx % O;
    int rest = idx / O;
    int f = rest % Fp;
    int m = rest / Fp;
    g_Wr[idx] = (f < F) ? __float2bfloat16(W[(size_t)(f * 5 + m) * O + o])
                        : __float2bfloat16(0.f);
}

// ------------------------ W-GEMM (mma.sync bf16) ----------------------------
// pre[n,b,o] = bias[o] + sum_{m,f} Xh_m[n][f][b] * Wr[m][f][o]
// CTA = 4 nodes -> 128 rows (row = ln*32 + b); K = 5*Fp in 16-chunks,
// 4-stage cp.async. A frags via ldmatrix.trans from natural [f][b] slabs.
// MODE 0 (gate, O=128): sigmoid; o<64 -> r*hx into buf0 (fp32+mirror), o>=64 -> g_U.
// MODE 1 (cand, O=64):  tanh; h = u*hx + (1-u)*c -> hout.

#define W_ST 136

template <int O, int MODE>
__global__ void __launch_bounds__(256)
wgemm_mma(int F, int Fp, int ld, int ldh,
          const float* __restrict__ bias,
          const float* __restrict__ hx, float* __restrict__ hout, int FinB)
{
    constexpr int NI = O / 32;        // n-tiles (8-wide) per warp: 4 or 2
    __shared__ __nv_bfloat16 As[4][16 * W_ST];
    __shared__ __nv_bfloat16 Ws[4][16 * W_ST];

    const int tid = threadIdx.x;
    const int n0  = blockIdx.x * 4;
    const int wid = tid >> 5, lane = tid & 31;
    const int wm  = (wid & 1) * 64;
    const int wn  = (wid >> 1) * (O / 4);

    const int chunksPerM = Fp / 16;
    const int total = 5 * chunksPerM;

    // loaders: one cp16 per thread for A; predicated cp16 for W
    const int kfA = tid >> 4, lnA = (tid >> 2) & 3, qA = tid & 3;
    const int kfW = tid >> 4, qW = tid & 15;

    // A frag (trans, from [k][m] storage) lane mapping
    const int ktA = (lane & 7) + ((lane >> 4) & 1) * 8;
    const int mcA = ((lane >> 3) & 1) * 8;
    // B frag (trans, from [k][o] storage)
    const int bR = ((lane >> 3) & 1) * 8 + (lane & 7);
    const int bC = (lane >> 4) * 8;

    const uint32_t asB = smem_u32(As), wsB = smem_u32(Ws);

    float acc[4][NI][4];
    #pragma unroll
    for (int mt = 0; mt < 4; mt++)
        #pragma unroll
        for (int ni = 0; ni < NI; ni++)
            #pragma unroll
            for (int q = 0; q < 4; q++) acc[mt][ni][q] = 0.f;

    auto LOAD = [&](int ic) {
        const int s = ic & 3;
        const int mi = ic / chunksPerM;
        const int fc = (ic % chunksPerM) * 16;
        const int f = fc + kfA;
        cp16(asB + (uint32_t)(s * 16 * W_ST + kfA * W_ST + lnA * 32 + qA * 8) * 2,
             g_Xh + (size_t)mi * MIRSZ + (size_t)(n0 + lnA) * ldh + (size_t)f * 32 + qA * 8,
             (f < F) ? 16 : 0);
        if (qW * 8 < O)
            cp16(wsB + (uint32_t)(s * 16 * W_ST + kfW * W_ST + qW * 8) * 2,
                 g_Wr + ((size_t)mi * Fp + fc + kfW) * O + qW * 8, 16);
    };

    LOAD(0); CP_COMMIT();
    LOAD(1); CP_COMMIT();
    LOAD(2); CP_COMMIT();

    for (int ic = 0; ic < total; ic++) {
        CP_WAIT2();
        __syncthreads();
        if (ic + 3 < total) LOAD(ic + 3);
        CP_COMMIT();

        const int s = ic & 3;
        uint32_t af[4][4];
        #pragma unroll
        for (int mt = 0; mt < 4; mt++)
            ldm4t(af[mt], asB +
                  (uint32_t)(s * 16 * W_ST + ktA * W_ST + wm + mt * 16 + mcA) * 2);
        uint32_t bf[(NI + 1) / 2][4];
        #pragma unroll
        for (int np = 0; np < (NI + 1) / 2; np++)
            ldm4t(bf[np], wsB +
                  (uint32_t)(s * 16 * W_ST + bR * W_ST + wn + np * 16 + bC) * 2);
        #pragma unroll
        for (int mt = 0; mt < 4; mt++)
            #pragma unroll
            for (int ni = 0; ni < NI; ni++)
                mma16816(acc[mt][ni], af[mt], &bf[ni >> 1][(ni & 1) * 2]);
        __syncthreads();
    }

    const int g = lane >> 2, t2 = (lane & 3) * 2;
    #pragma unroll
    for (int mt = 0; mt < 4; mt++) {
        #pragma unroll
        for (int half = 0; half < 2; half++) {
            int r = wm + mt * 16 + g + half * 8;
            int ln = r >> 5, b = r & 31, n = n0 + ln;
            #pragma unroll
            for (int ni = 0; ni < NI; ni++) {
                int o = wn + ni * 8 + t2;
                float p0 = acc[mt][ni][half * 2 + 0] + bias[o];
                float p1 = acc[mt][ni][half * 2 + 1] + bias[o + 1];
                if (MODE == 0) {
                    float v0 = 1.0f / (1.0f + __expf(-p0));
                    float v1 = 1.0f / (1.0f + __expf(-p1));
                    if (o < 64) {
                        float hp0 = hx[(size_t)b * (NN * UU) + (size_t)n * UU + o];
                        float hp1 = hx[(size_t)b * (NN * UU) + (size_t)n * UU + o + 1];
                        float r0 = v0 * hp0, r1 = v1 * hp1;
                        g_X[(size_t)n * ld + (size_t)(FinB + o * 32) + b] = r0;
                        g_X[(size_t)n * ld + (size_t)(FinB + (o + 1) * 32) + b] = r1;
                        g_Xh[(size_t)n * ldh + (size_t)(FinB + o * 32) + b] = __float2bfloat16(r0);
                        g_Xh[(size_t)n * ldh + (size_t)(FinB + (o + 1) * 32) + b] = __float2bfloat16(r1);
                    } else {
                        *(float2*)&g_U[((size_t)n * 32 + b) * 64 + (o - 64)] = make_float2(v0, v1);
                    }
                } else {
                    float c0 = tanhf(p0), c1 = tanhf(p1);
                    float2 uv = *(const float2*)&g_U[((size_t)n * 32 + b) * 64 + o];
                    float hp0 = hx[(size_t)b * (NN * UU) + (size_t)n * UU + o];
                    float hp1 = hx[(size_t)b * (NN * UU) + (size_t)n * UU + o + 1];
                    float h0v = uv.x * hp0 + (1.0f - uv.x) * c0;
                    float h1v = uv.y * hp1 + (1.0f - uv.y) * c1;
                    *(float2*)&hout[(size_t)b * (NN * UU) + (size_t)n * UU + o] = make_float2(h0v, h1v);
                }
            }
        }
    }
}

// ------------------------------ projection ----------------------------------

__global__ void proj_kernel(const float* __restrict__ h1, const float* __restrict__ wp,
                            const float* __restrict__ bp, float* __restrict__ out)
{
    int warp = (blockIdx.x * blockDim.x + threadIdx.x) >> 5;
    int lane = threadIdx.x & 31;
    if (warp >= BB * NN) return;
    int b = warp >> 11, n = warp & (NN - 1);
    const float* hr = h1 + (size_t)b * (NN * UU) + (size_t)n * UU;
    float s = hr[lane] * wp[lane] + hr[lane + 32] * wp[lane + 32];
    #pragma unroll
    for (int o = 16; o > 0; o >>= 1) s += __shfl_down_sync(0xffffffffu, s, o);
    if (lane == 0) out[(size_t)b * NN + n] = s + bp[0];
}

// ------------------------------ driver --------------------------------------

static void run_diffusion(int colOff, int colW, int ld, int ldh) {
    int tiles = (colW + 127) / 128;
    dim3 g(tiles, 16);
    int ce = colOff + colW;
    diff_mma<<<g, 256, DIFF_SMEM>>>(0, 0,  1, -1, 1, ld, ldh, colOff, ce, 1.0f,  0.0f); // buf1 = S0@buf0
    diff_mma<<<g, 256, DIFF_SMEM>>>(0, 1, -1,  0, 2, ld, ldh, colOff, ce, 2.0f, -1.0f); // buf2 = 2*S0@buf1 - buf0
    diff_mma<<<g, 256, DIFF_SMEM>>>(1, 1, -1, -1, 3, ld, ldh, colOff, ce, 1.0f,  0.0f); // buf3 = S1@buf1
    diff_mma<<<g, 256, DIFF_SMEM>>>(1, 3, -1,  1, 4, ld, ldh, colOff, ce, 2.0f, -1.0f); // buf4 = 2*S1@buf3 - buf1
}

extern "C" void kernel_launch(void* const* d_in, const int* in_sizes, int n_in,
                              void* d_out, int out_size)
{
    const float* inputs = (const float*)d_in[0];
    const float* hidden = (const float*)d_in[1];
    const float* adj    = (const float*)d_in[2];
    const float* wg0    = (const float*)d_in[3];
    const float* bg0    = (const float*)d_in[4];
    const float* wc0    = (const float*)d_in[5];
    const float* bc0    = (const float*)d_in[6];
    const float* wg1    = (const float*)d_in[7];
    const float* bg1    = (const float*)d_in[8];
    const float* wc1    = (const float*)d_in[9];
    const float* bc1    = (const float*)d_in[10];
    const float* wproj  = (const float*)d_in[11];
    const float* bproj  = (const float*)d_in[12];

    float* out = (float*)d_out;                       // (B, N)
    float* h0  = out + (size_t)BB * NN;               // (B, N*U)
    float* h1  = h0 + (size_t)BB * NN * UU;           // (B, N*U)
    const float* hx0 = hidden;
    const float* hx1 = hidden + (size_t)BB * NN * UU;

    cudaFuncSetAttribute(diff_mma, cudaFuncAttributeMaxDynamicSharedMemorySize, DIFF_SMEM);

    // supports
    rowsum_kernel<<<NN, 256>>>(adj);
    colsum_kernel<<<NN / 32, dim3(32, 8)>>>(adj);
    build_supports<<<dim3(NN / 32, NN / 32), dim3(32, 8)>>>(adj);

    // ---- layer 0 (F = 65 -> Fp = 80; fp32 ld = 2080, bf16 ldh = 2112) ----
    pack0_kernel<<<NN, 256>>>(inputs, hx0);
    run_diffusion(0, 2080, 2080, 2112);
    wprep_kernel<<<(5 * 80 * 128 + 255) / 256, 256>>>(wg0, 65, 80, 128);
    wgemm_mma<128, 0><<<NN / 4, 256>>>(65, 80, 2080, 2112, bg0, hx0, nullptr, 32);
    run_diffusion(32, 2048, 2080, 2112);
    wprep_kernel<<<(5 * 80 * 64 + 255) / 256, 256>>>(wc0, 65, 80, 64);
    wgemm_mma<64, 1><<<NN / 4, 256>>>(65, 80, 2080, 2112, bc0, hx0, h0, 0);

    // ---- layer 1 (F = 128 = Fp; ld = ldh = 4096) ----
    pack1_kernel<<<NN, 256>>>(h0, hx1);
    run_diffusion(0, 4096, 4096, 4096);
    wprep_kernel<<<(5 * 128 * 128 + 255) / 256, 256>>>(wg1, 128, 128, 128);
    wgemm_mma<128, 0><<<NN / 4, 256>>>(128, 128, 4096, 4096, bg1, hx1, nullptr, 2048);
    run_diffusion(2048, 2048, 4096, 4096);
    wprep_kernel<<<(5 * 128 * 64 + 255) / 256, 256>>>(wc1, 128, 128, 64);
    wgemm_mma<64, 1><<<NN / 4, 256>>>(128, 128, 4096, 4096, bc1, hx1, h1, 0);

    // projection
    proj_kernel<<<(BB * NN) / 8, 256>>>(h1, wproj, bproj, out);
}

// round 11
// speedup vs baseline: 6.8422x; 1.0624x over previous
#include <cuda_runtime.h>
#include <cuda_bf16.h>
#include <cstdint>

// ----------------------------------------------------------------------------
// DCRNN decoder cell (2 layers), N=2048, B=32, UNITS=64, 5 Chebyshev terms.
// Diffusion + W-GEMMs on mma.sync bf16 (sm_80 baseline ISA; tcgen05 is gated
// off by the harness's .target sm_103 lowering).
// Chain (reference quirk — x0 mutates between supports):
//   buf1 = S0@buf0 ; buf2 = 2*S0@buf1 - buf0 ; buf3 = S1@buf1 ; buf4 = 2*S1@buf3 - buf1
// fp32 kept only for buf0/buf1 (the 'prev' operands); all GEMM inputs bf16.
// ----------------------------------------------------------------------------

#define NN   2048
#define BB   32
#define UU   64
static const size_t BUFSZ = 2048ull * 4096ull;   // fp32 per-term buffer (buf0, buf1)
static const size_t MIRSZ = 2048ull * 4096ull;   // bf16 mirror buffer (buf0..buf4)

__device__ __nv_bfloat16 g_S0h[2048ull * 2048ull];
__device__ __nv_bfloat16 g_S1h[2048ull * 2048ull];
__device__ float g_inv_row[NN];
__device__ float g_inv_col[NN];
__device__ float g_X[2ull * 2048ull * 4096ull];          // fp32: buf0, buf1
__device__ __nv_bfloat16 g_Xh[5ull * 2048ull * 4096ull]; // bf16 mirrors buf0..4
__device__ float g_U[2048ull * 32ull * 64ull];           // u gate, [n][b][o]
__device__ __nv_bfloat16 g_Wr[5ull * 128ull * 128ull];   // reordered bf16 weights

// ----------------------------- PTX helpers ----------------------------------

__device__ __forceinline__ uint32_t smem_u32(const void* p) {
    uint32_t r;
    asm("{ .reg .u64 t; cvta.to.shared.u64 t, %1; cvt.u32.u64 %0, t; }" : "=r"(r) : "l"(p));
    return r;
}

__device__ __forceinline__ void cp16(uint32_t sm, const void* g, int srcsize) {
    asm volatile("cp.async.cg.shared.global [%0], [%1], 16, %2;"
                 :: "r"(sm), "l"(g), "r"(srcsize) : "memory");
}
#define CP_COMMIT() asm volatile("cp.async.commit_group;" ::: "memory")
#define CP_WAIT2()  asm volatile("cp.async.wait_group 2;" ::: "memory")

__device__ __forceinline__ void ldmA(uint32_t* r, uint32_t addr) {
    asm volatile("ldmatrix.sync.aligned.m8n8.x4.shared.b16 {%0,%1,%2,%3}, [%4];"
                 : "=r"(r[0]), "=r"(r[1]), "=r"(r[2]), "=r"(r[3]) : "r"(addr));
}

__device__ __forceinline__ void ldm4t(uint32_t* r, uint32_t addr) {
    asm volatile("ldmatrix.sync.aligned.m8n8.x4.trans.shared.b16 {%0,%1,%2,%3}, [%4];"
                 : "=r"(r[0]), "=r"(r[1]), "=r"(r[2]), "=r"(r[3]) : "r"(addr));
}

__device__ __forceinline__ void mma16816(float* c, const uint32_t* a, const uint32_t* b) {
    asm volatile(
        "mma.sync.aligned.m16n8k16.row.col.f32.bf16.bf16.f32 "
        "{%0,%1,%2,%3},{%4,%5,%6,%7},{%8,%9},{%0,%1,%2,%3};"
        : "+f"(c[0]), "+f"(c[1]), "+f"(c[2]), "+f"(c[3])
        : "r"(a[0]), "r"(a[1]), "r"(a[2]), "r"(a[3]), "r"(b[0]), "r"(b[1]));
}

// ------------------------------ support prep --------------------------------

__global__ void rowsum_kernel(const float* __restrict__ adj) {
    int row = blockIdx.x, tid = threadIdx.x;
    float s = 0.f;
    for (int k = tid; k < NN; k += 256) s += adj[(size_t)row * NN + k];
    __shared__ float sm[256];
    sm[tid] = s; __syncthreads();
    for (int o = 128; o > 0; o >>= 1) { if (tid < o) sm[tid] += sm[tid + o]; __syncthreads(); }
    if (tid == 0) g_inv_row[row] = 1.0f / fmaxf(sm[0], 1e-8f);
}

__global__ void colsum_kernel(const float* __restrict__ adj) {
    int j = blockIdx.x * 32 + threadIdx.x;
    int ty = threadIdx.y;
    float s = 0.f;
    for (int k = ty; k < NN; k += 8) s += adj[(size_t)k * NN + j];
    __shared__ float sm[8][32];
    sm[ty][threadIdx.x] = s; __syncthreads();
    if (ty == 0) {
        float t = 0.f;
        #pragma unroll
        for (int r = 0; r < 8; r++) t += sm[r][threadIdx.x];
        g_inv_col[j] = 1.0f / fmaxf(t, 1e-8f);
    }
}

__global__ void build_supports(const float* __restrict__ adj) {
    __shared__ float t[32][33];
    int tx = threadIdx.x, ty = threadIdx.y;
    int j0 = blockIdx.x * 32, i0 = blockIdx.y * 32;
    #pragma unroll
    for (int s = 0; s < 4; s++) {
        int r = ty + s * 8;
        t[r][tx] = adj[(size_t)(i0 + r) * NN + j0 + tx];
    }
    __syncthreads();
    float icol = g_inv_col[j0 + tx];
    float irow = g_inv_row[i0 + tx];
    #pragma unroll
    for (int s = 0; s < 4; s++) {
        int r = ty + s * 8;
        g_S1h[(size_t)(i0 + r) * NN + j0 + tx] = __float2bfloat16(t[r][tx] * icol);
        g_S0h[(size_t)(j0 + r) * NN + i0 + tx] = __float2bfloat16(t[tx][r] * irow);
    }
}

// ------------------------- x0 packing (coalesced) ----------------------------

__global__ void pack0_kernel(const float* __restrict__ inp, const float* __restrict__ hx0) {
    __shared__ float sm[65 * 33];
    int n = blockIdx.x, tid = threadIdx.x;
    for (int idx = tid; idx < 2048; idx += 256) {
        int b = idx >> 6, u = idx & 63;       // consecutive u -> coalesced hx0 reads
        sm[(u + 1) * 33 + b] = hx0[(size_t)b * (NN * UU) + (size_t)n * UU + u];
    }
    if (tid < 32) sm[tid] = inp[(size_t)tid * NN + n];
    __syncthreads();
    for (int idx = tid; idx < 65 * 32; idx += 256) {
        int f = idx >> 5, b = idx & 31;
        float v = sm[f * 33 + b];
        g_X[(size_t)n * 2080 + idx] = v;
        g_Xh[(size_t)n * 2112 + idx] = __float2bfloat16(v);
    }
}

__global__ void pack1_kernel(const float* __restrict__ h0, const float* __restrict__ hx1) {
    __shared__ float sm[128 * 33];
    int n = blockIdx.x, tid = threadIdx.x;
    for (int idx = tid; idx < 2048; idx += 256) {
        int b = idx >> 6, u = idx & 63;
        sm[u * 33 + b]        = h0 [(size_t)b * (NN * UU) + (size_t)n * UU + u];
        sm[(u + 64) * 33 + b] = hx1[(size_t)b * (NN * UU) + (size_t)n * UU + u];
    }
    __syncthreads();
    for (int idx = tid; idx < 128 * 32; idx += 256) {
        int f = idx >> 5, b = idx & 31;
        float v = sm[f * 33 + b];
        g_X[(size_t)n * 4096 + idx] = v;
        g_Xh[(size_t)n * 4096 + idx] = __float2bfloat16(v);
    }
}

// ------------------- diffusion GEMM (mma.sync bf16) -------------------------
// mirror_y = bf16(alpha*(S @ Xh[:,cols]) + beta*Xprev[:,cols]); optional fp32 Y.
// CTA 128x128, k-chunk 32, 4-stage cp.async; 8 warps (2M x 4N); occ target 2.

#define D_AST 40
#define D_BST 136
#define D_ASB (128 * D_AST * 2)
#define D_BSB (32 * D_BST * 2)
#define DIFF_SMEM (4 * (D_ASB + D_BSB))   // 75776 bytes

__device__ __forceinline__ void diff_body(
    const __nv_bfloat16* __restrict__ S, const __nv_bfloat16* __restrict__ Xh,
    float* __restrict__ Y, const float* __restrict__ Xp, __nv_bfloat16* __restrict__ Yh,
    int ld, int ldh, int colOff, int colEnd, float alpha, float beta,
    uint32_t aBase, uint32_t bBase)
{
    const int tid  = threadIdx.x;
    const int row0 = blockIdx.y * 128;
    const int col0 = colOff + blockIdx.x * 128;

    const int wid = tid >> 5, lane = tid & 31;
    const int wm = (wid & 1) * 64;
    const int wn = (wid >> 1) * 32;

    const int aR = (lane & 7) + ((lane >> 3) & 1) * 8;
    const int aC = (lane >> 4) * 8;
    const int bR = ((lane >> 3) & 1) * 8 + (lane & 7);
    const int bC = (lane >> 4) * 8;

    float acc[4][4][4];
    #pragma unroll
    for (int mi = 0; mi < 4; mi++)
        #pragma unroll
        for (int ni = 0; ni < 4; ni++)
            #pragma unroll
            for (int q = 0; q < 4; q++) acc[mi][ni][q] = 0.f;

    auto LOAD = [&](int i) {
        const int k0 = i * 32, s = i & 3;
        #pragma unroll
        for (int t = 0; t < 2; t++) {
            int aIdx = t * 256 + tid;
            int r = aIdx >> 2, kq = aIdx & 3;
            cp16(aBase + s * D_ASB + (uint32_t)(r * D_AST + kq * 8) * 2,
                 S + (size_t)(row0 + r) * NN + k0 + kq * 8, 16);
        }
        #pragma unroll
        for (int t = 0; t < 2; t++) {
            int bIdx = t * 256 + tid;
            int kr = bIdx >> 4, nq = bIdx & 15;
            int c = col0 + nq * 8;
            cp16(bBase + s * D_BSB + (uint32_t)(kr * D_BST + nq * 8) * 2,
                 Xh + (size_t)(k0 + kr) * ldh + c, (c < colEnd) ? 16 : 0);
        }
    };

    LOAD(0); CP_COMMIT();
    LOAD(1); CP_COMMIT();
    LOAD(2); CP_COMMIT();

    for (int i = 0; i < 64; i++) {
        CP_WAIT2();
        __syncthreads();                // orders iter i-1 reads before LOAD overwrite
        if (i + 3 < 64) LOAD(i + 3);
        CP_COMMIT();

        const int s = i & 3;
        #pragma unroll
        for (int kc = 0; kc < 32; kc += 16) {
            uint32_t af[4][4], bf[2][4];
            #pragma unroll
            for (int mi = 0; mi < 4; mi++)
                ldmA(af[mi], aBase + s * D_ASB +
                     (uint32_t)((wm + mi * 16 + aR) * D_AST + kc + aC) * 2);
            #pragma unroll
            for (int np = 0; np < 2; np++)
                ldm4t(bf[np], bBase + s * D_BSB +
                      (uint32_t)((kc + bR) * D_BST + wn + np * 16 + bC) * 2);
            #pragma unroll
            for (int mi = 0; mi < 4; mi++)
                #pragma unroll
                for (int ni = 0; ni < 4; ni++)
                    mma16816(acc[mi][ni], af[mi], &bf[ni >> 1][(ni & 1) * 2]);
        }
        // no trailing sync: next iteration's top barrier provides it
    }

    const int g = lane >> 2, t2 = (lane & 3) * 2;
    #pragma unroll
    for (int mi = 0; mi < 4; mi++) {
        #pragma unroll
        for (int half = 0; half < 2; half++) {
            int r = row0 + wm + mi * 16 + g + half * 8;
            float* yRow = Y ? (Y + (size_t)r * ld) : nullptr;
            const float* pRow = Xp ? (Xp + (size_t)r * ld) : nullptr;
            __nv_bfloat16* hRow = Yh + (size_t)r * ldh;
            #pragma unroll
            for (int ni = 0; ni < 4; ni++) {
                int c = col0 + wn + ni * 8 + t2;
                if (c < colEnd) {
                    float vx = alpha * acc[mi][ni][half * 2 + 0];
                    float vy = alpha * acc[mi][ni][half * 2 + 1];
                    if (pRow) {
                        float2 p = *(const float2*)(pRow + c);
                        vx = fmaf(beta, p.x, vx);
                        vy = fmaf(beta, p.y, vy);
                    }
                    if (yRow) *(float2*)(yRow + c) = make_float2(vx, vy);
                    *(__nv_bfloat162*)(hRow + c) = __floats2bfloat162_rn(vx, vy);
                }
            }
        }
    }
}

__global__ void __launch_bounds__(256, 2)
diff_mma(int sSel, int xhIdx, int yIdx, int prevIdx, int yhIdx,
         int ld, int ldh, int colOff, int colEnd, float alpha, float beta)
{
    extern __shared__ __nv_bfloat16 dsm[];
    const uint32_t aBase = smem_u32(dsm);
    diff_body(sSel ? g_S1h : g_S0h,
              g_Xh + (size_t)xhIdx * MIRSZ,
              (yIdx >= 0) ? (g_X + (size_t)yIdx * BUFSZ) : nullptr,
              (prevIdx >= 0) ? (g_X + (size_t)prevIdx * BUFSZ) : nullptr,
              g_Xh + (size_t)yhIdx * MIRSZ,
              ld, ldh, colOff, colEnd, alpha, beta, aBase, aBase + 4 * D_ASB);
}

// buf2 and buf3 both depend only on buf1 -> one launch, z selects the job
__global__ void __launch_bounds__(256, 2)
diff_pair(int ld, int ldh, int colOff, int colEnd)
{
    extern __shared__ __nv_bfloat16 dsm[];
    const uint32_t aBase = smem_u32(dsm);
    if (blockIdx.z == 0) {
        // buf2 = 2*S0@buf1 - buf0
        diff_body(g_S0h, g_Xh + 1 * MIRSZ, nullptr, g_X + 0 * BUFSZ, g_Xh + 2 * MIRSZ,
                  ld, ldh, colOff, colEnd, 2.0f, -1.0f, aBase, aBase + 4 * D_ASB);
    } else {
        // buf3 = S1@buf1
        diff_body(g_S1h, g_Xh + 1 * MIRSZ, nullptr, nullptr, g_Xh + 3 * MIRSZ,
                  ld, ldh, colOff, colEnd, 1.0f, 0.0f, aBase, aBase + 4 * D_ASB);
    }
}

// ----------------------- weight reorder (fp32 -> bf16) ----------------------

__global__ void wprep_kernel(const float* __restrict__ W, int F, int Fp, int O) {
    int idx = blockIdx.x * 256 + threadIdx.x;
    if (idx >= 5 * Fp * O) return;
    int o = idx % O;
    int rest = idx / O;
    int f = rest % Fp;
    int m = rest / Fp;
    g_Wr[idx] = (f < F) ? __float2bfloat16(W[(size_t)(f * 5 + m) * O + o])
                        : __float2bfloat16(0.f);
}

// ------------------------ W-GEMM (mma.sync bf16) ----------------------------

#define W_ST 136

template <int O, int MODE>
__global__ void __launch_bounds__(256)
wgemm_mma(int F, int Fp, int ld, int ldh,
          const float* __restrict__ bias,
          const float* __restrict__ hx, float* __restrict__ hout, int FinB)
{
    constexpr int NI = O / 32;
    __shared__ __nv_bfloat16 As[4][16 * W_ST];
    __shared__ __nv_bfloat16 Ws[4][16 * W_ST];

    const int tid = threadIdx.x;
    const int n0  = blockIdx.x * 4;
    const int wid = tid >> 5, lane = tid & 31;
    const int wm  = (wid & 1) * 64;
    const int wn  = (wid >> 1) * (O / 4);

    const int chunksPerM = Fp / 16;
    const int total = 5 * chunksPerM;

    const int kfA = tid >> 4, lnA = (tid >> 2) & 3, qA = tid & 3;
    const int kfW = tid >> 4, qW = tid & 15;

    const int ktA = (lane & 7) + ((lane >> 4) & 1) * 8;
    const int mcA = ((lane >> 3) & 1) * 8;
    const int bR = ((lane >> 3) & 1) * 8 + (lane & 7);
    const int bC = (lane >> 4) * 8;

    const uint32_t asB = smem_u32(As), wsB = smem_u32(Ws);

    float acc[4][NI][4];
    #pragma unroll
    for (int mt = 0; mt < 4; mt++)
        #pragma unroll
        for (int ni = 0; ni < NI; ni++)
            #pragma unroll
            for (int q = 0; q < 4; q++) acc[mt][ni][q] = 0.f;

    auto LOAD = [&](int ic) {
        const int s = ic & 3;
        const int mi = ic / chunksPerM;
        const int fc = (ic % chunksPerM) * 16;
        const int f = fc + kfA;
        cp16(asB + (uint32_t)(s * 16 * W_ST + kfA * W_ST + lnA * 32 + qA * 8) * 2,
             g_Xh + (size_t)mi * MIRSZ + (size_t)(n0 + lnA) * ldh + (size_t)f * 32 + qA * 8,
             (f < F) ? 16 : 0);
        if (qW * 8 < O)
            cp16(wsB + (uint32_t)(s * 16 * W_ST + kfW * W_ST + qW * 8) * 2,
                 g_Wr + ((size_t)mi * Fp + fc + kfW) * O + qW * 8, 16);
    };

    LOAD(0); CP_COMMIT();
    LOAD(1); CP_COMMIT();
    LOAD(2); CP_COMMIT();

    for (int ic = 0; ic < total; ic++) {
        CP_WAIT2();
        __syncthreads();
        if (ic + 3 < total) LOAD(ic + 3);
        CP_COMMIT();

        const int s = ic & 3;
        uint32_t af[4][4];
        #pragma unroll
        for (int mt = 0; mt < 4; mt++)
            ldm4t(af[mt], asB +
                  (uint32_t)(s * 16 * W_ST + ktA * W_ST + wm + mt * 16 + mcA) * 2);
        uint32_t bf[(NI + 1) / 2][4];
        #pragma unroll
        for (int np = 0; np < (NI + 1) / 2; np++)
            ldm4t(bf[np], wsB +
                  (uint32_t)(s * 16 * W_ST + bR * W_ST + wn + np * 16 + bC) * 2);
        #pragma unroll
        for (int mt = 0; mt < 4; mt++)
            #pragma unroll
            for (int ni = 0; ni < NI; ni++)
                mma16816(acc[mt][ni], af[mt], &bf[ni >> 1][(ni & 1) * 2]);
        // no trailing sync (top barrier of next iteration covers the hazard)
    }

    const int g = lane >> 2, t2 = (lane & 3) * 2;
    #pragma unroll
    for (int mt = 0; mt < 4; mt++) {
        #pragma unroll
        for (int half = 0; half < 2; half++) {
            int r = wm + mt * 16 + g + half * 8;
            int ln = r >> 5, b = r & 31, n = n0 + ln;
            #pragma unroll
            for (int ni = 0; ni < NI; ni++) {
                int o = wn + ni * 8 + t2;
                float p0 = acc[mt][ni][half * 2 + 0] + bias[o];
                float p1 = acc[mt][ni][half * 2 + 1] + bias[o + 1];
                if (MODE == 0) {
                    float v0 = 1.0f / (1.0f + __expf(-p0));
                    float v1 = 1.0f / (1.0f + __expf(-p1));
                    if (o < 64) {
                        float hp0 = hx[(size_t)b * (NN * UU) + (size_t)n * UU + o];
                        float hp1 = hx[(size_t)b * (NN * UU) + (size_t)n * UU + o + 1];
                        float r0 = v0 * hp0, r1 = v1 * hp1;
                        g_X[(size_t)n * ld + (size_t)(FinB + o * 32) + b] = r0;
                        g_X[(size_t)n * ld + (size_t)(FinB + (o + 1) * 32) + b] = r1;
                        g_Xh[(size_t)n * ldh + (size_t)(FinB + o * 32) + b] = __float2bfloat16(r0);
                        g_Xh[(size_t)n * ldh + (size_t)(FinB + (o + 1) * 32) + b] = __float2bfloat16(r1);
                    } else {
                        *(float2*)&g_U[((size_t)n * 32 + b) * 64 + (o - 64)] = make_float2(v0, v1);
                    }
                } else {
                    float c0 = tanhf(p0), c1 = tanhf(p1);
                    float2 uv = *(const float2*)&g_U[((size_t)n * 32 + b) * 64 + o];
                    float hp0 = hx[(size_t)b * (NN * UU) + (size_t)n * UU + o];
                    float hp1 = hx[(size_t)b * (NN * UU) + (size_t)n * UU + o + 1];
                    float h0v = uv.x * hp0 + (1.0f - uv.x) * c0;
                    float h1v = uv.y * hp1 + (1.0f - uv.y) * c1;
                    *(float2*)&hout[(size_t)b * (NN * UU) + (size_t)n * UU + o] = make_float2(h0v, h1v);
                }
            }
        }
    }
}

// ------------------------------ projection ----------------------------------

__global__ void proj_kernel(const float* __restrict__ h1, const float* __restrict__ wp,
                            const float* __restrict__ bp, float* __restrict__ out)
{
    int warp = (blockIdx.x * blockDim.x + threadIdx.x) >> 5;
    int lane = threadIdx.x & 31;
    if (warp >= BB * NN) return;
    int b = warp >> 11, n = warp & (NN - 1);
    const float* hr = h1 + (size_t)b * (NN * UU) + (size_t)n * UU;
    float s = hr[lane] * wp[lane] + hr[lane + 32] * wp[lane + 32];
    #pragma unroll
    for (int o = 16; o > 0; o >>= 1) s += __shfl_down_sync(0xffffffffu, s, o);
    if (lane == 0) out[(size_t)b * NN + n] = s + bp[0];
}

// ------------------------------ driver --------------------------------------

static void run_diffusion(int colOff, int colW, int ld, int ldh) {
    int tiles = (colW + 127) / 128;
    int ce = colOff + colW;
    diff_mma <<<dim3(tiles, 16),    256, DIFF_SMEM>>>(0, 0, 1, -1, 1, ld, ldh, colOff, ce, 1.0f, 0.0f); // buf1
    diff_pair<<<dim3(tiles, 16, 2), 256, DIFF_SMEM>>>(ld, ldh, colOff, ce);                             // buf2+buf3
    diff_mma <<<dim3(tiles, 16),    256, DIFF_SMEM>>>(1, 3, -1, 1, 4, ld, ldh, colOff, ce, 2.0f, -1.0f);// buf4
}

extern "C" void kernel_launch(void* const* d_in, const int* in_sizes, int n_in,
                              void* d_out, int out_size)
{
    const float* inputs = (const float*)d_in[0];
    const float* hidden = (const float*)d_in[1];
    const float* adj    = (const float*)d_in[2];
    const float* wg0    = (const float*)d_in[3];
    const float* bg0    = (const float*)d_in[4];
    const float* wc0    = (const float*)d_in[5];
    const float* bc0    = (const float*)d_in[6];
    const float* wg1    = (const float*)d_in[7];
    const float* bg1    = (const float*)d_in[8];
    const float* wc1    = (const float*)d_in[9];
    const float* bc1    = (const float*)d_in[10];
    const float* wproj  = (const float*)d_in[11];
    const float* bproj  = (const float*)d_in[12];

    float* out = (float*)d_out;                       // (B, N)
    float* h0  = out + (size_t)BB * NN;               // (B, N*U)
    float* h1  = h0 + (size_t)BB * NN * UU;           // (B, N*U)
    const float* hx0 = hidden;
    const float* hx1 = hidden + (size_t)BB * NN * UU;

    cudaFuncSetAttribute(diff_mma,  cudaFuncAttributeMaxDynamicSharedMemorySize, DIFF_SMEM);
    cudaFuncSetAttribute(diff_pair, cudaFuncAttributeMaxDynamicSharedMemorySize, DIFF_SMEM);

    // supports
    rowsum_kernel<<<NN, 256>>>(adj);
    colsum_kernel<<<NN / 32, dim3(32, 8)>>>(adj);
    build_supports<<<dim3(NN / 32, NN / 32), dim3(32, 8)>>>(adj);

    // ---- layer 0 (F = 65 -> Fp = 80; fp32 ld = 2080, bf16 ldh = 2112) ----
    pack0_kernel<<<NN, 256>>>(inputs, hx0);
    run_diffusion(0, 2080, 2080, 2112);
    wprep_kernel<<<(5 * 80 * 128 + 255) / 256, 256>>>(wg0, 65, 80, 128);
    wgemm_mma<128, 0><<<NN / 4, 256>>>(65, 80, 2080, 2112, bg0, hx0, nullptr, 32);
    run_diffusion(32, 2048, 2080, 2112);
    wprep_kernel<<<(5 * 80 * 64 + 255) / 256, 256>>>(wc0, 65, 80, 64);
    wgemm_mma<64, 1><<<NN / 4, 256>>>(65, 80, 2080, 2112, bc0, hx0, h0, 0);

    // ---- layer 1 (F = 128 = Fp; ld = ldh = 4096) ----
    pack1_kernel<<<NN, 256>>>(h0, hx1);
    run_diffusion(0, 4096, 4096, 4096);
    wprep_kernel<<<(5 * 128 * 128 + 255) / 256, 256>>>(wg1, 128, 128, 128);
    wgemm_mma<128, 0><<<NN / 4, 256>>>(128, 128, 4096, 4096, bg1, hx1, nullptr, 2048);
    run_diffusion(2048, 2048, 4096, 4096);
    wprep_kernel<<<(5 * 128 * 64 + 255) / 256, 256>>>(wc1, 128, 128, 64);
    wgemm_mma<64, 1><<<NN / 4, 256>>>(128, 128, 4096, 4096, bc1, hx1, h1, 0);

    // projection
    proj_kernel<<<(BB * NN) / 8, 256>>>(h1, wproj, bproj, out);
}